// round 15
// baseline (speedup 1.0000x reference)
#include <cuda_runtime.h>
#include <cstdint>

// ---------------------------------------------------------------------------
// GNBlock: h = BN(PReLU(segment_sum(relu(x[src]@W1+b1)@W2+b2, dst) + x@W_root + b_root))
// N=50000, E=800000, C_IN=64, C_HID=128, C_OUT=64
//
// msg (persistent; X stored as duplicated f32x2 pairs -> no pack2 MOVs in
// GEMM1/GEMM3; single X buffer with register prefetch overlapped with GEMM2)
// -> x4-MLP edge scatter (RED.v4) -> read-only PReLU stats -> BN(+PReLU) out.
// ---------------------------------------------------------------------------

#define N_MAX 50000
#define C_IN 64
#define C_HID 128
#define C_OUT 64
#define TILE_N 128
#define MT 512
#define NT 256

__device__ __align__(16) float g_h[N_MAX * C_OUT];    // root transform (pre-PReLU)
__device__ __align__(16) float g_msg[N_MAX * C_OUT];  // per-node messages
__device__ float g_stats[2 * C_OUT];
__device__ int g_idx64;

// ---- f32x2 packed helpers ---------------------------------------------------
__device__ __forceinline__ unsigned long long pack2(float v) {
    unsigned long long r;
    unsigned int u = __float_as_uint(v);
    asm("mov.b64 %0, {%1, %2};" : "=l"(r) : "r"(u), "r"(u));
    return r;
}
__device__ __forceinline__ unsigned long long fma2(unsigned long long a,
                                                   unsigned long long b,
                                                   unsigned long long c) {
    unsigned long long d;
    asm("fma.rn.f32x2 %0, %1, %2, %3;" : "=l"(d) : "l"(a), "l"(b), "l"(c));
    return d;
}
__device__ __forceinline__ float2 unpack2(unsigned long long v) {
    unsigned int lo, hi;
    asm("mov.b64 {%0, %1}, %2;" : "=r"(lo), "=r"(hi) : "l"(v));
    float2 f;
    f.x = __uint_as_float(lo);
    f.y = __uint_as_float(hi);
    return f;
}

// ---------------------------------------------------------------------------
// K1: PERSISTENT fused per-node kernel.
//   block 0 zeroes g_stats and probes index dtype.
//   X tile lives in smem as DUPLICATED f32x2 pairs (u64 per element):
//   GEMM1/GEMM3 read packed operands directly (no MOVs).
//   msg[n] = relu(x[n]@W1 + b1) @ W2 + b2  -> g_msg
//   h[n]   = x[n]@W_root + b_root          -> g_h
// smem (floats): W1 8192 | W2 8192 | Wr 4096 | Xdup 128x66 u64 (16896 fl)
//                | sH 128x132 (16896 fl) | biases 256   -> 213 KB
// ---------------------------------------------------------------------------
#define SXP 66  // u64 pitch: 4 rows apart => 528 words => bank +16 (no conflict)
#define SH_PITCH 132
#define SMEM_FLOATS (8192 + 8192 + 4096 + TILE_N * SXP * 2 + TILE_N * SH_PITCH + 256)
#define SMEM_BYTES (SMEM_FLOATS * 4)

__global__ __launch_bounds__(MT) void msg_kernel(
    const float* __restrict__ x, const float* __restrict__ W1,
    const float* __restrict__ b1, const float* __restrict__ W2,
    const float* __restrict__ b2, const float* __restrict__ Wr,
    const float* __restrict__ br, const void* __restrict__ ei, int N,
    int numTiles) {
    extern __shared__ float sm[];
    float* sW1 = sm;                                   // 64 x 128
    float* sW2 = sW1 + 64 * 128;                       // 128 x 64
    float* sWr = sW2 + 128 * 64;                       // 64 x 64
    unsigned long long* sX =
        reinterpret_cast<unsigned long long*>(sWr + 64 * 64);  // 128 x 66 u64
    float* sH = sWr + 64 * 64 + TILE_N * SXP * 2;      // 128 x 132
    float* sb1 = sH + TILE_N * SH_PITCH;               // 128
    float* sb2 = sb1 + 128;                            // 64
    float* sbr = sb2 + 64;                             // 64

    const int tid = threadIdx.x;

    // folded setup (block 0): zero stats + dtype probe
    if (blockIdx.x == 0) {
        if (tid < 128) g_stats[tid] = 0.f;
        if (tid >= 128 && tid < 160) {
            const long long* p = (const long long*)ei;
            long long v = p[tid - 128];
            unsigned ok = __ballot_sync(0xffffffffu, v >= 0 && v < (long long)N);
            if (tid == 128) g_idx64 = (ok == 0xffffffffu) ? 1 : 0;
        }
    }

    // stage weights + biases once
    for (int i = tid; i < 2048; i += MT)
        reinterpret_cast<float4*>(sW1)[i] = reinterpret_cast<const float4*>(W1)[i];
    for (int i = tid; i < 2048; i += MT)
        reinterpret_cast<float4*>(sW2)[i] = reinterpret_cast<const float4*>(W2)[i];
    for (int i = tid; i < 1024; i += MT)
        reinterpret_cast<float4*>(sWr)[i] = reinterpret_cast<const float4*>(Wr)[i];
    if (tid < 128) sb1[tid] = b1[tid];
    else if (tid < 192) sb2[tid - 128] = b2[tid - 128];
    else if (tid < 256) sbr[tid - 192] = br[tid - 192];

    const int hg = tid & 15;
    const int rg = tid >> 4;
    const int hb = hg * 8;
    const int kb = hg * 4;
    const int rb = rg * 4;
    const int sr = tid >> 4;   // staging row (0..31), 4 float4 per thread row set
    const int sq = tid & 15;   // staging quad

    int tile = blockIdx.x;

    // stage first tile (duplicated pairs)
    if (tile < numTiles) {
#pragma unroll
        for (int j = 0; j < 4; j++) {
            int r = j * 32 + sr;
            int n = tile * TILE_N + r;
            if (n >= N) n = N - 1;
            float4 v = __ldg(&reinterpret_cast<const float4*>(x + (long long)n * C_IN)[sq]);
            ulonglong2 lo, hi;
            lo.x = pack2(v.x); lo.y = pack2(v.y);
            hi.x = pack2(v.z); hi.y = pack2(v.w);
            *reinterpret_cast<ulonglong2*>(&sX[r * SXP + sq * 4]) = lo;
            *reinterpret_cast<ulonglong2*>(&sX[r * SXP + sq * 4 + 2]) = hi;
        }
    }
    __syncthreads();

    for (; tile < numTiles; tile += gridDim.x) {
        const int n0 = tile * TILE_N;
        const int next = tile + gridDim.x;

        // prefetch next tile's X into registers (hidden behind GEMM1/GEMM3)
        float4 pf[4];
        if (next < numTiles) {
#pragma unroll
            for (int j = 0; j < 4; j++) {
                int r = j * 32 + sr;
                int n = next * TILE_N + r;
                if (n >= N) n = N - 1;
                pf[j] = __ldg(&reinterpret_cast<const float4*>(x + (long long)n * C_IN)[sq]);
            }
        }

        // ---- GEMM1: sH = relu(sX @ W1 + b1)  (packed X, no MOVs) ----
        {
            unsigned long long acc[4][4];
#pragma unroll
            for (int e = 0; e < 4; e++)
#pragma unroll
                for (int p = 0; p < 4; p++) acc[e][p] = 0ULL;

#pragma unroll 8
            for (int k = 0; k < C_IN; k += 2) {
                ulonglong2 wa0 = *reinterpret_cast<const ulonglong2*>(&sW1[k * C_HID + hb]);
                ulonglong2 wa1 =
                    *reinterpret_cast<const ulonglong2*>(&sW1[k * C_HID + hb + 4]);
                ulonglong2 wb0 =
                    *reinterpret_cast<const ulonglong2*>(&sW1[(k + 1) * C_HID + hb]);
                ulonglong2 wb1 =
                    *reinterpret_cast<const ulonglong2*>(&sW1[(k + 1) * C_HID + hb + 4]);
#pragma unroll
                for (int e = 0; e < 4; e++) {
                    ulonglong2 xp =
                        *reinterpret_cast<const ulonglong2*>(&sX[(rb + e) * SXP + k]);
                    acc[e][0] = fma2(xp.x, wa0.x, acc[e][0]);
                    acc[e][1] = fma2(xp.x, wa0.y, acc[e][1]);
                    acc[e][2] = fma2(xp.x, wa1.x, acc[e][2]);
                    acc[e][3] = fma2(xp.x, wa1.y, acc[e][3]);
                    acc[e][0] = fma2(xp.y, wb0.x, acc[e][0]);
                    acc[e][1] = fma2(xp.y, wb0.y, acc[e][1]);
                    acc[e][2] = fma2(xp.y, wb1.x, acc[e][2]);
                    acc[e][3] = fma2(xp.y, wb1.y, acc[e][3]);
                }
            }
#pragma unroll
            for (int e = 0; e < 4; e++) {
#pragma unroll
                for (int p = 0; p < 4; p++) {
                    float2 v = unpack2(acc[e][p]);
                    v.x = fmaxf(v.x + sb1[hb + 2 * p], 0.f);
                    v.y = fmaxf(v.y + sb1[hb + 2 * p + 1], 0.f);
                    *reinterpret_cast<float2*>(&sH[(rb + e) * SH_PITCH + hb + 2 * p]) = v;
                }
            }
        }

        // ---- GEMM3: g_h = sX @ W_root + b_root (packed X) ----
        {
            unsigned long long a3[4][2];
#pragma unroll
            for (int e = 0; e < 4; e++) { a3[e][0] = 0ULL; a3[e][1] = 0ULL; }

#pragma unroll 8
            for (int k = 0; k < C_IN; k += 2) {
                ulonglong2 wa = *reinterpret_cast<const ulonglong2*>(&sWr[k * C_OUT + kb]);
                ulonglong2 wb =
                    *reinterpret_cast<const ulonglong2*>(&sWr[(k + 1) * C_OUT + kb]);
#pragma unroll
                for (int e = 0; e < 4; e++) {
                    ulonglong2 xp =
                        *reinterpret_cast<const ulonglong2*>(&sX[(rb + e) * SXP + k]);
                    a3[e][0] = fma2(xp.x, wa.x, a3[e][0]);
                    a3[e][1] = fma2(xp.x, wa.y, a3[e][1]);
                    a3[e][0] = fma2(xp.y, wb.x, a3[e][0]);
                    a3[e][1] = fma2(xp.y, wb.y, a3[e][1]);
                }
            }
            float c0 = sbr[kb], c1 = sbr[kb + 1], c2 = sbr[kb + 2], c3 = sbr[kb + 3];
#pragma unroll
            for (int e = 0; e < 4; e++) {
                int n = n0 + rb + e;
                if (n >= N) continue;
                float2 v0 = unpack2(a3[e][0]);
                float2 v1 = unpack2(a3[e][1]);
                float4 r;
                r.x = v0.x + c0; r.y = v0.y + c1; r.z = v1.x + c2; r.w = v1.y + c3;
                *reinterpret_cast<float4*>(&g_h[(long long)n * C_OUT + kb]) = r;
            }
        }
        __syncthreads();  // all sX reads + sH writes complete

        // store prefetched X (overlaps with GEMM2 below, which only touches sH)
        if (next < numTiles) {
#pragma unroll
            for (int j = 0; j < 4; j++) {
                int r = j * 32 + sr;
                ulonglong2 lo, hi;
                lo.x = pack2(pf[j].x); lo.y = pack2(pf[j].y);
                hi.x = pack2(pf[j].z); hi.y = pack2(pf[j].w);
                *reinterpret_cast<ulonglong2*>(&sX[r * SXP + sq * 4]) = lo;
                *reinterpret_cast<ulonglong2*>(&sX[r * SXP + sq * 4 + 2]) = hi;
            }
        }

        // ---- GEMM2: g_msg = sH @ W2 + b2 ----
        {
            unsigned long long a2[4][2];
#pragma unroll
            for (int e = 0; e < 4; e++) { a2[e][0] = 0ULL; a2[e][1] = 0ULL; }

#pragma unroll 8
            for (int j = 0; j < C_HID; j += 2) {
                ulonglong2 wa = *reinterpret_cast<const ulonglong2*>(&sW2[j * C_OUT + kb]);
                ulonglong2 wb =
                    *reinterpret_cast<const ulonglong2*>(&sW2[(j + 1) * C_OUT + kb]);
#pragma unroll
                for (int e = 0; e < 4; e++) {
                    float2 hv = *reinterpret_cast<const float2*>(&sH[(rb + e) * SH_PITCH + j]);
                    unsigned long long h0 = pack2(hv.x), h1 = pack2(hv.y);
                    a2[e][0] = fma2(h0, wa.x, a2[e][0]);
                    a2[e][1] = fma2(h0, wa.y, a2[e][1]);
                    a2[e][0] = fma2(h1, wb.x, a2[e][0]);
                    a2[e][1] = fma2(h1, wb.y, a2[e][1]);
                }
            }
            float c0 = sb2[kb], c1 = sb2[kb + 1], c2 = sb2[kb + 2], c3 = sb2[kb + 3];
#pragma unroll
            for (int e = 0; e < 4; e++) {
                int n = n0 + rb + e;
                if (n >= N) continue;
                float2 v0 = unpack2(a2[e][0]);
                float2 v1 = unpack2(a2[e][1]);
                float4 r;
                r.x = v0.x + c0; r.y = v0.y + c1; r.z = v1.x + c2; r.w = v1.y + c3;
                *reinterpret_cast<float4*>(&g_msg[(long long)n * C_OUT + kb]) = r;
            }
        }
        __syncthreads();  // sX stores + sH reads complete before next iteration
    }
}

// ---------------------------------------------------------------------------
// K2: scatter  g_h[dst] += g_msg[src].  16 threads per edge-slot; each slot
// handles 4 edges at stride G -> 4 independent idx->msg->RED chains (MLP=4).
// ---------------------------------------------------------------------------
__global__ __launch_bounds__(NT) void scatter_kernel(const void* __restrict__ ei_raw,
                                                     int E, int G) {
    long long idx = (long long)blockIdx.x * NT + threadIdx.x;
    int base = (int)(idx >> 4);
    int q = (int)(idx & 15);
    if (base >= G) return;

    const int idx64 = g_idx64;
    int e0 = base, e1 = base + G, e2 = base + 2 * G, e3 = base + 3 * G;
    bool v0 = e0 < E, v1 = e1 < E, v2 = e2 < E, v3 = e3 < E;

    int s0 = 0, d0 = 0, s1 = 0, d1 = 0, s2 = 0, d2 = 0, s3 = 0, d3 = 0;
    if (idx64) {
        const long long* p = (const long long*)ei_raw;
        if (v0) { s0 = (int)__ldg(&p[e0]); d0 = (int)__ldg(&p[E + e0]); }
        if (v1) { s1 = (int)__ldg(&p[e1]); d1 = (int)__ldg(&p[E + e1]); }
        if (v2) { s2 = (int)__ldg(&p[e2]); d2 = (int)__ldg(&p[E + e2]); }
        if (v3) { s3 = (int)__ldg(&p[e3]); d3 = (int)__ldg(&p[E + e3]); }
    } else {
        const int* p = (const int*)ei_raw;
        if (v0) { s0 = __ldg(&p[e0]); d0 = __ldg(&p[E + e0]); }
        if (v1) { s1 = __ldg(&p[e1]); d1 = __ldg(&p[E + e1]); }
        if (v2) { s2 = __ldg(&p[e2]); d2 = __ldg(&p[E + e2]); }
        if (v3) { s3 = __ldg(&p[e3]); d3 = __ldg(&p[E + e3]); }
    }

    float4 m0, m1, m2, m3;
    if (v0) m0 = *reinterpret_cast<const float4*>(&g_msg[(long long)s0 * C_OUT + q * 4]);
    if (v1) m1 = *reinterpret_cast<const float4*>(&g_msg[(long long)s1 * C_OUT + q * 4]);
    if (v2) m2 = *reinterpret_cast<const float4*>(&g_msg[(long long)s2 * C_OUT + q * 4]);
    if (v3) m3 = *reinterpret_cast<const float4*>(&g_msg[(long long)s3 * C_OUT + q * 4]);

    if (v0) {
        float* pd = &g_h[(long long)d0 * C_OUT + q * 4];
        asm volatile("red.global.add.v4.f32 [%0], {%1,%2,%3,%4};"
                     :: "l"(pd), "f"(m0.x), "f"(m0.y), "f"(m0.z), "f"(m0.w) : "memory");
    }
    if (v1) {
        float* pd = &g_h[(long long)d1 * C_OUT + q * 4];
        asm volatile("red.global.add.v4.f32 [%0], {%1,%2,%3,%4};"
                     :: "l"(pd), "f"(m1.x), "f"(m1.y), "f"(m1.z), "f"(m1.w) : "memory");
    }
    if (v2) {
        float* pd = &g_h[(long long)d2 * C_OUT + q * 4];
        asm volatile("red.global.add.v4.f32 [%0], {%1,%2,%3,%4};"
                     :: "l"(pd), "f"(m2.x), "f"(m2.y), "f"(m2.z), "f"(m2.w) : "memory");
    }
    if (v3) {
        float* pd = &g_h[(long long)d3 * C_OUT + q * 4];
        asm volatile("red.global.add.v4.f32 [%0], {%1,%2,%3,%4};"
                     :: "l"(pd), "f"(m3.x), "f"(m3.y), "f"(m3.z), "f"(m3.w) : "memory");
    }
}

// ---------------------------------------------------------------------------
// K3: READ-ONLY stats pass: per-channel sum/sumsq of PReLU(g_h).
// ---------------------------------------------------------------------------
__global__ void prelu_stats_kernel(const float* __restrict__ prelu_w, int N) {
    const float a = prelu_w[0];
    const int total4 = N * (C_OUT / 4);
    const int stride = gridDim.x * blockDim.x;
    const float4* gh4 = reinterpret_cast<const float4*>(g_h);
    float s0 = 0.f, s1 = 0.f, s2 = 0.f, s3 = 0.f;
    float q0 = 0.f, q1 = 0.f, q2 = 0.f, q3 = 0.f;
    for (int i = blockIdx.x * blockDim.x + threadIdx.x; i < total4; i += stride) {
        float4 v = gh4[i];
        v.x = (v.x >= 0.f) ? v.x : a * v.x;
        v.y = (v.y >= 0.f) ? v.y : a * v.y;
        v.z = (v.z >= 0.f) ? v.z : a * v.z;
        v.w = (v.w >= 0.f) ? v.w : a * v.w;
        s0 += v.x; s1 += v.y; s2 += v.z; s3 += v.w;
        q0 += v.x * v.x; q1 += v.y * v.y; q2 += v.z * v.z; q3 += v.w * v.w;
    }
    __shared__ float rs[NT * 4], rq[NT * 4];
    int t = threadIdx.x;
    rs[t * 4 + 0] = s0; rs[t * 4 + 1] = s1; rs[t * 4 + 2] = s2; rs[t * 4 + 3] = s3;
    rq[t * 4 + 0] = q0; rq[t * 4 + 1] = q1; rq[t * 4 + 2] = q2; rq[t * 4 + 3] = q3;
    __syncthreads();
    if (t < 64) {
        int qq = t >> 2, comp = t & 3;
        float ts = 0.f, tq = 0.f;
#pragma unroll
        for (int m = 0; m < 16; m++) {
            int src = (m * 16 + qq) * 4 + comp;
            ts += rs[src];
            tq += rq[src];
        }
        atomicAdd(&g_stats[t], ts);
        atomicAdd(&g_stats[64 + t], tq);
    }
}

// ---------------------------------------------------------------------------
// K4: finalize — recompute PReLU, normalize, write out
// ---------------------------------------------------------------------------
__global__ void bn_kernel(float* __restrict__ out, const float* __restrict__ gamma,
                          const float* __restrict__ beta,
                          const float* __restrict__ prelu_w, int N) {
    __shared__ float sscale[C_OUT], sshift[C_OUT];
    if (threadIdx.x < C_OUT) {
        float invN = 1.f / (float)N;
        float mu = g_stats[threadIdx.x] * invN;
        float var = g_stats[64 + threadIdx.x] * invN - mu * mu;
        float inv = rsqrtf(var + 1e-5f);
        float g = gamma[threadIdx.x] * inv;
        sscale[threadIdx.x] = g;
        sshift[threadIdx.x] = beta[threadIdx.x] - mu * g;
    }
    __syncthreads();
    const float a = prelu_w[0];
    const int total4 = N * (C_OUT / 4);
    const int stride = gridDim.x * blockDim.x;
    const float4* gh4 = reinterpret_cast<const float4*>(g_h);
    float4* o4 = reinterpret_cast<float4*>(out);
    for (int i = blockIdx.x * blockDim.x + threadIdx.x; i < total4; i += stride) {
        int q = (i & 15);
        float4 sc = reinterpret_cast<const float4*>(sscale)[q];
        float4 sh = reinterpret_cast<const float4*>(sshift)[q];
        float4 v = gh4[i];
        v.x = (v.x >= 0.f) ? v.x : a * v.x;
        v.y = (v.y >= 0.f) ? v.y : a * v.y;
        v.z = (v.z >= 0.f) ? v.z : a * v.z;
        v.w = (v.w >= 0.f) ? v.w : a * v.w;
        float4 r;
        r.x = fmaf(v.x, sc.x, sh.x);
        r.y = fmaf(v.y, sc.y, sh.y);
        r.z = fmaf(v.z, sc.z, sh.z);
        r.w = fmaf(v.w, sc.w, sh.w);
        o4[i] = r;
    }
}

// ---------------------------------------------------------------------------
extern "C" void kernel_launch(void* const* d_in, const int* in_sizes, int n_in,
                              void* d_out, int out_size) {
    const float* x = (const float*)d_in[0];
    const void* ei = d_in[1];
    const float* W1 = (const float*)d_in[2];
    const float* b1 = (const float*)d_in[3];
    const float* W2 = (const float*)d_in[4];
    const float* b2 = (const float*)d_in[5];
    const float* Wr = (const float*)d_in[6];
    const float* br = (const float*)d_in[7];
    const float* pw = (const float*)d_in[8];
    const float* gamma = (const float*)d_in[9];
    const float* beta = (const float*)d_in[10];
    float* out = (float*)d_out;

    const int N = in_sizes[0] / C_IN;
    const int E = in_sizes[1] / 2;
    const int numTiles = (N + TILE_N - 1) / TILE_N;
    const int G = (E + 3) / 4;

    static int nSM = 0;
    if (nSM == 0) cudaDeviceGetAttribute(&nSM, cudaDevAttrMultiProcessorCount, 0);

    cudaFuncSetAttribute(msg_kernel, cudaFuncAttributeMaxDynamicSharedMemorySize,
                         SMEM_BYTES);

    // K1: persistent per-node MLP + root transform (setup folded into block 0)
    msg_kernel<<<nSM, MT, SMEM_BYTES>>>(x, W1, b1, W2, b2, Wr, br, ei, N, numTiles);

    // K2: edge scatter, 4 edges per 16-thread slot
    const long long units = (long long)G * 16;
    scatter_kernel<<<(int)((units + NT - 1) / NT), NT>>>(ei, E, G);

    // K3: stats (read-only)
    prelu_stats_kernel<<<592, NT>>>(pw, N);

    // K4: PReLU + BN normalize -> out
    bn_kernel<<<592, NT>>>(out, gamma, beta, pw, N);
}

// round 16
// speedup vs baseline: 1.2453x; 1.2453x over previous
#include <cuda_runtime.h>
#include <cstdint>

// ---------------------------------------------------------------------------
// GNBlock: h = BN(PReLU(segment_sum(relu(x[src]@W1+b1)@W2+b2, dst) + x@W_root + b_root))
// N=50000, E=800000, C_IN=64, C_HID=128, C_OUT=64
//
// R13 base (best=115.4us) with ONE change: GEMM1+GEMM3 fused into a single
// k-loop with 8-row thread tiles (warp-broadcast X, half the weight-LDS
// crossbar traffic). GEMM2 / staging / scatter / epilogue identical to R13.
// ---------------------------------------------------------------------------

#define N_MAX 50000
#define C_IN 64
#define C_HID 128
#define C_OUT 64
#define TILE_N 128
#define MT 512
#define NT 256

__device__ __align__(16) float g_h[N_MAX * C_OUT];    // root transform (pre-PReLU)
__device__ __align__(16) float g_msg[N_MAX * C_OUT];  // per-node messages
__device__ float g_stats[2 * C_OUT];
__device__ int g_idx64;

// ---- f32x2 packed helpers ---------------------------------------------------
__device__ __forceinline__ unsigned long long pack2(float v) {
    unsigned long long r;
    unsigned int u = __float_as_uint(v);
    asm("mov.b64 %0, {%1, %2};" : "=l"(r) : "r"(u), "r"(u));
    return r;
}
__device__ __forceinline__ unsigned long long fma2(unsigned long long a,
                                                   unsigned long long b,
                                                   unsigned long long c) {
    unsigned long long d;
    asm("fma.rn.f32x2 %0, %1, %2, %3;" : "=l"(d) : "l"(a), "l"(b), "l"(c));
    return d;
}
__device__ __forceinline__ float2 unpack2(unsigned long long v) {
    unsigned int lo, hi;
    asm("mov.b64 {%0, %1}, %2;" : "=r"(lo), "=r"(hi) : "l"(v));
    float2 f;
    f.x = __uint_as_float(lo);
    f.y = __uint_as_float(hi);
    return f;
}

// ---------------------------------------------------------------------------
// K1: PERSISTENT fused per-node kernel (double-buffered X, R13 pipeline):
//   fused GEMM1+GEMM3 (8-row tiles): sH = relu(sX@W1+b1); g_h = sX@Wr+br
//   GEMM2 (4x4 tiles, R13): g_msg = sH@W2 + b2
// ---------------------------------------------------------------------------
#define SX_PITCH 68
#define SH_PITCH 132
#define XBUF (TILE_N * SX_PITCH)
#define SMEM_FLOATS (8192 + 8192 + 4096 + 2 * XBUF + TILE_N * SH_PITCH + 256)
#define SMEM_BYTES (SMEM_FLOATS * 4)

__global__ __launch_bounds__(MT) void msg_kernel(
    const float* __restrict__ x, const float* __restrict__ W1,
    const float* __restrict__ b1, const float* __restrict__ W2,
    const float* __restrict__ b2, const float* __restrict__ Wr,
    const float* __restrict__ br, const void* __restrict__ ei, int N,
    int numTiles) {
    extern __shared__ float sm[];
    float* sW1 = sm;                       // 64 x 128
    float* sW2 = sW1 + 64 * 128;           // 128 x 64
    float* sWr = sW2 + 128 * 64;           // 64 x 64
    float* sX0 = sWr + 64 * 64;            // 2 x (128 x 68)
    float* sH = sX0 + 2 * XBUF;            // 128 x 132
    float* sb1 = sH + TILE_N * SH_PITCH;   // 128
    float* sb2 = sb1 + 128;                // 64
    float* sbr = sb2 + 64;                 // 64

    const int tid = threadIdx.x;

    // folded setup (block 0): zero stats + dtype probe
    if (blockIdx.x == 0) {
        if (tid < 128) g_stats[tid] = 0.f;
        if (tid >= 128 && tid < 160) {
            const long long* p = (const long long*)ei;
            long long v = p[tid - 128];
            unsigned ok = __ballot_sync(0xffffffffu, v >= 0 && v < (long long)N);
            if (tid == 128) g_idx64 = (ok == 0xffffffffu) ? 1 : 0;
        }
    }

    // stage weights + biases once
    for (int i = tid; i < 2048; i += MT)
        reinterpret_cast<float4*>(sW1)[i] = reinterpret_cast<const float4*>(W1)[i];
    for (int i = tid; i < 2048; i += MT)
        reinterpret_cast<float4*>(sW2)[i] = reinterpret_cast<const float4*>(W2)[i];
    for (int i = tid; i < 1024; i += MT)
        reinterpret_cast<float4*>(sWr)[i] = reinterpret_cast<const float4*>(Wr)[i];
    if (tid < 128) sb1[tid] = b1[tid];
    else if (tid < 192) sb2[tid - 128] = b2[tid - 128];
    else if (tid < 256) sbr[tid - 192] = br[tid - 192];

    // fused GEMM1+3 mapping: 8 rows x (4 hid / 2 out) per thread;
    // warp shares its row group -> X loads broadcast.
    const int hg13 = tid & 31;    // 0..31
    const int rg13 = tid >> 5;    // 0..15
    const int hb13 = hg13 * 4;    // GEMM1 cols
    const int cb13 = hg13 * 2;    // GEMM3 cols
    const int rb13 = rg13 * 8;    // rows

    // GEMM2 mapping (R13): 4 rows x 4 cols
    const int hg2 = tid & 15;
    const int rg2 = tid >> 4;
    const int kb2 = hg2 * 4;
    const int rb2 = rg2 * 4;

    int tile = blockIdx.x;
    int bufIdx = 0;

    // stage first tile
    if (tile < numTiles) {
#pragma unroll
        for (int j = 0; j < 4; j++) {
            int i = j * MT + tid;
            int r = i >> 4, q = i & 15;
            int n = tile * TILE_N + r;
            if (n >= N) n = N - 1;
            float4 v = reinterpret_cast<const float4*>(x + (long long)n * C_IN)[q];
            *reinterpret_cast<float4*>(&sX0[r * SX_PITCH + q * 4]) = v;
        }
    }
    __syncthreads();

    for (; tile < numTiles; tile += gridDim.x, bufIdx ^= 1) {
        const int n0 = tile * TILE_N;
        float* sXc = sX0 + bufIdx * XBUF;
        float* sXn = sX0 + (bufIdx ^ 1) * XBUF;
        const int next = tile + gridDim.x;

        // prefetch next tile's X (hidden behind fused GEMM1+3)
        float4 pf[4];
        if (next < numTiles) {
#pragma unroll
            for (int j = 0; j < 4; j++) {
                int i = j * MT + tid;
                int r = i >> 4, q = i & 15;
                int n = next * TILE_N + r;
                if (n >= N) n = N - 1;
                pf[j] = __ldg(&reinterpret_cast<const float4*>(x + (long long)n * C_IN)[q]);
            }
        }

        // ---- fused GEMM1 + GEMM3 over shared X rows ----
        {
            unsigned long long a1[8][2];
            unsigned long long a3[8];
#pragma unroll
            for (int e = 0; e < 8; e++) {
                a1[e][0] = 0ULL;
                a1[e][1] = 0ULL;
                a3[e] = 0ULL;
            }

#pragma unroll 4
            for (int k = 0; k < C_IN; k += 2) {
                ulonglong2 w1a =
                    *reinterpret_cast<const ulonglong2*>(&sW1[k * C_HID + hb13]);
                ulonglong2 w1b =
                    *reinterpret_cast<const ulonglong2*>(&sW1[(k + 1) * C_HID + hb13]);
                unsigned long long w3a =
                    *reinterpret_cast<const unsigned long long*>(&sWr[k * C_OUT + cb13]);
                unsigned long long w3b =
                    *reinterpret_cast<const unsigned long long*>(&sWr[(k + 1) * C_OUT + cb13]);
#pragma unroll
                for (int e = 0; e < 8; e++) {
                    float2 xv =
                        *reinterpret_cast<const float2*>(&sXc[(rb13 + e) * SX_PITCH + k]);
                    unsigned long long x0 = pack2(xv.x), x1 = pack2(xv.y);
                    a1[e][0] = fma2(x0, w1a.x, a1[e][0]);
                    a1[e][1] = fma2(x0, w1a.y, a1[e][1]);
                    a1[e][0] = fma2(x1, w1b.x, a1[e][0]);
                    a1[e][1] = fma2(x1, w1b.y, a1[e][1]);
                    a3[e] = fma2(x0, w3a, a3[e]);
                    a3[e] = fma2(x1, w3b, a3[e]);
                }
            }

            // GEMM1 epilogue: bias + relu -> sH (float4 per row)
            float bb0 = sb1[hb13], bb1 = sb1[hb13 + 1], bb2 = sb1[hb13 + 2],
                  bb3 = sb1[hb13 + 3];
#pragma unroll
            for (int e = 0; e < 8; e++) {
                float2 v0 = unpack2(a1[e][0]);
                float2 v1 = unpack2(a1[e][1]);
                float4 r;
                r.x = fmaxf(v0.x + bb0, 0.f);
                r.y = fmaxf(v0.y + bb1, 0.f);
                r.z = fmaxf(v1.x + bb2, 0.f);
                r.w = fmaxf(v1.y + bb3, 0.f);
                *reinterpret_cast<float4*>(&sH[(rb13 + e) * SH_PITCH + hb13]) = r;
            }

            // GEMM3 epilogue: bias -> g_h (float2 per row)
            float c0 = sbr[cb13], c1 = sbr[cb13 + 1];
#pragma unroll
            for (int e = 0; e < 8; e++) {
                int n = n0 + rb13 + e;
                if (n >= N) continue;
                float2 v = unpack2(a3[e]);
                float2 r;
                r.x = v.x + c0;
                r.y = v.y + c1;
                *reinterpret_cast<float2*>(&g_h[(long long)n * C_OUT + cb13]) = r;
            }
        }

        // store prefetched X into the other buffer
        if (next < numTiles) {
#pragma unroll
            for (int j = 0; j < 4; j++) {
                int i = j * MT + tid;
                int r = i >> 4, q = i & 15;
                *reinterpret_cast<float4*>(&sXn[r * SX_PITCH + q * 4]) = pf[j];
            }
        }
        __syncthreads();  // sH complete; next-X staged

        // ---- GEMM2: g_msg = sH @ W2 + b2 (R13 form) ----
        {
            unsigned long long a2[4][2];
#pragma unroll
            for (int e = 0; e < 4; e++) { a2[e][0] = 0ULL; a2[e][1] = 0ULL; }

#pragma unroll 8
            for (int j = 0; j < C_HID; j += 2) {
                ulonglong2 wa = *reinterpret_cast<const ulonglong2*>(&sW2[j * C_OUT + kb2]);
                ulonglong2 wb =
                    *reinterpret_cast<const ulonglong2*>(&sW2[(j + 1) * C_OUT + kb2]);
#pragma unroll
                for (int e = 0; e < 4; e++) {
                    float2 hv = *reinterpret_cast<const float2*>(&sH[(rb2 + e) * SH_PITCH + j]);
                    unsigned long long h0 = pack2(hv.x), h1 = pack2(hv.y);
                    a2[e][0] = fma2(h0, wa.x, a2[e][0]);
                    a2[e][1] = fma2(h0, wa.y, a2[e][1]);
                    a2[e][0] = fma2(h1, wb.x, a2[e][0]);
                    a2[e][1] = fma2(h1, wb.y, a2[e][1]);
                }
            }
            float c0 = sb2[kb2], c1 = sb2[kb2 + 1], c2 = sb2[kb2 + 2], c3 = sb2[kb2 + 3];
#pragma unroll
            for (int e = 0; e < 4; e++) {
                int n = n0 + rb2 + e;
                if (n >= N) continue;
                float2 v0 = unpack2(a2[e][0]);
                float2 v1 = unpack2(a2[e][1]);
                float4 r;
                r.x = v0.x + c0; r.y = v0.y + c1; r.z = v1.x + c2; r.w = v1.y + c3;
                *reinterpret_cast<float4*>(&g_msg[(long long)n * C_OUT + kb2]) = r;
            }
        }
        __syncthreads();  // GEMM2's sH reads done before next GEMM1 writes sH
    }
}

// ---------------------------------------------------------------------------
// K2: scatter  g_h[dst] += g_msg[src].  16 threads per edge-slot; each slot
// handles 4 edges at stride G -> 4 independent idx->msg->RED chains (MLP=4).
// ---------------------------------------------------------------------------
__global__ __launch_bounds__(NT) void scatter_kernel(const void* __restrict__ ei_raw,
                                                     int E, int G) {
    long long idx = (long long)blockIdx.x * NT + threadIdx.x;
    int base = (int)(idx >> 4);
    int q = (int)(idx & 15);
    if (base >= G) return;

    const int idx64 = g_idx64;
    int e0 = base, e1 = base + G, e2 = base + 2 * G, e3 = base + 3 * G;
    bool v0 = e0 < E, v1 = e1 < E, v2 = e2 < E, v3 = e3 < E;

    int s0 = 0, d0 = 0, s1 = 0, d1 = 0, s2 = 0, d2 = 0, s3 = 0, d3 = 0;
    if (idx64) {
        const long long* p = (const long long*)ei_raw;
        if (v0) { s0 = (int)__ldg(&p[e0]); d0 = (int)__ldg(&p[E + e0]); }
        if (v1) { s1 = (int)__ldg(&p[e1]); d1 = (int)__ldg(&p[E + e1]); }
        if (v2) { s2 = (int)__ldg(&p[e2]); d2 = (int)__ldg(&p[E + e2]); }
        if (v3) { s3 = (int)__ldg(&p[e3]); d3 = (int)__ldg(&p[E + e3]); }
    } else {
        const int* p = (const int*)ei_raw;
        if (v0) { s0 = __ldg(&p[e0]); d0 = __ldg(&p[E + e0]); }
        if (v1) { s1 = __ldg(&p[e1]); d1 = __ldg(&p[E + e1]); }
        if (v2) { s2 = __ldg(&p[e2]); d2 = __ldg(&p[E + e2]); }
        if (v3) { s3 = __ldg(&p[e3]); d3 = __ldg(&p[E + e3]); }
    }

    float4 m0, m1, m2, m3;
    if (v0) m0 = *reinterpret_cast<const float4*>(&g_msg[(long long)s0 * C_OUT + q * 4]);
    if (v1) m1 = *reinterpret_cast<const float4*>(&g_msg[(long long)s1 * C_OUT + q * 4]);
    if (v2) m2 = *reinterpret_cast<const float4*>(&g_msg[(long long)s2 * C_OUT + q * 4]);
    if (v3) m3 = *reinterpret_cast<const float4*>(&g_msg[(long long)s3 * C_OUT + q * 4]);

    if (v0) {
        float* pd = &g_h[(long long)d0 * C_OUT + q * 4];
        asm volatile("red.global.add.v4.f32 [%0], {%1,%2,%3,%4};"
                     :: "l"(pd), "f"(m0.x), "f"(m0.y), "f"(m0.z), "f"(m0.w) : "memory");
    }
    if (v1) {
        float* pd = &g_h[(long long)d1 * C_OUT + q * 4];
        asm volatile("red.global.add.v4.f32 [%0], {%1,%2,%3,%4};"
                     :: "l"(pd), "f"(m1.x), "f"(m1.y), "f"(m1.z), "f"(m1.w) : "memory");
    }
    if (v2) {
        float* pd = &g_h[(long long)d2 * C_OUT + q * 4];
        asm volatile("red.global.add.v4.f32 [%0], {%1,%2,%3,%4};"
                     :: "l"(pd), "f"(m2.x), "f"(m2.y), "f"(m2.z), "f"(m2.w) : "memory");
    }
    if (v3) {
        float* pd = &g_h[(long long)d3 * C_OUT + q * 4];
        asm volatile("red.global.add.v4.f32 [%0], {%1,%2,%3,%4};"
                     :: "l"(pd), "f"(m3.x), "f"(m3.y), "f"(m3.z), "f"(m3.w) : "memory");
    }
}

// ---------------------------------------------------------------------------
// K3: READ-ONLY stats pass: per-channel sum/sumsq of PReLU(g_h).
// ---------------------------------------------------------------------------
__global__ void prelu_stats_kernel(const float* __restrict__ prelu_w, int N) {
    const float a = prelu_w[0];
    const int total4 = N * (C_OUT / 4);
    const int stride = gridDim.x * blockDim.x;
    const float4* gh4 = reinterpret_cast<const float4*>(g_h);
    float s0 = 0.f, s1 = 0.f, s2 = 0.f, s3 = 0.f;
    float q0 = 0.f, q1 = 0.f, q2 = 0.f, q3 = 0.f;
    for (int i = blockIdx.x * blockDim.x + threadIdx.x; i < total4; i += stride) {
        float4 v = gh4[i];
        v.x = (v.x >= 0.f) ? v.x : a * v.x;
        v.y = (v.y >= 0.f) ? v.y : a * v.y;
        v.z = (v.z >= 0.f) ? v.z : a * v.z;
        v.w = (v.w >= 0.f) ? v.w : a * v.w;
        s0 += v.x; s1 += v.y; s2 += v.z; s3 += v.w;
        q0 += v.x * v.x; q1 += v.y * v.y; q2 += v.z * v.z; q3 += v.w * v.w;
    }
    __shared__ float rs[NT * 4], rq[NT * 4];
    int t = threadIdx.x;
    rs[t * 4 + 0] = s0; rs[t * 4 + 1] = s1; rs[t * 4 + 2] = s2; rs[t * 4 + 3] = s3;
    rq[t * 4 + 0] = q0; rq[t * 4 + 1] = q1; rq[t * 4 + 2] = q2; rq[t * 4 + 3] = q3;
    __syncthreads();
    if (t < 64) {
        int qq = t >> 2, comp = t & 3;
        float ts = 0.f, tq = 0.f;
#pragma unroll
        for (int m = 0; m < 16; m++) {
            int src = (m * 16 + qq) * 4 + comp;
            ts += rs[src];
            tq += rq[src];
        }
        atomicAdd(&g_stats[t], ts);
        atomicAdd(&g_stats[64 + t], tq);
    }
}

// ---------------------------------------------------------------------------
// K4: finalize — recompute PReLU, normalize, write out
// ---------------------------------------------------------------------------
__global__ void bn_kernel(float* __restrict__ out, const float* __restrict__ gamma,
                          const float* __restrict__ beta,
                          const float* __restrict__ prelu_w, int N) {
    __shared__ float sscale[C_OUT], sshift[C_OUT];
    if (threadIdx.x < C_OUT) {
        float invN = 1.f / (float)N;
        float mu = g_stats[threadIdx.x] * invN;
        float var = g_stats[64 + threadIdx.x] * invN - mu * mu;
        float inv = rsqrtf(var + 1e-5f);
        float g = gamma[threadIdx.x] * inv;
        sscale[threadIdx.x] = g;
        sshift[threadIdx.x] = beta[threadIdx.x] - mu * g;
    }
    __syncthreads();
    const float a = prelu_w[0];
    const int total4 = N * (C_OUT / 4);
    const int stride = gridDim.x * blockDim.x;
    const float4* gh4 = reinterpret_cast<const float4*>(g_h);
    float4* o4 = reinterpret_cast<float4*>(out);
    for (int i = blockIdx.x * blockDim.x + threadIdx.x; i < total4; i += stride) {
        int q = (i & 15);
        float4 sc = reinterpret_cast<const float4*>(sscale)[q];
        float4 sh = reinterpret_cast<const float4*>(sshift)[q];
        float4 v = gh4[i];
        v.x = (v.x >= 0.f) ? v.x : a * v.x;
        v.y = (v.y >= 0.f) ? v.y : a * v.y;
        v.z = (v.z >= 0.f) ? v.z : a * v.z;
        v.w = (v.w >= 0.f) ? v.w : a * v.w;
        float4 r;
        r.x = fmaf(v.x, sc.x, sh.x);
        r.y = fmaf(v.y, sc.y, sh.y);
        r.z = fmaf(v.z, sc.z, sh.z);
        r.w = fmaf(v.w, sc.w, sh.w);
        o4[i] = r;
    }
}

// ---------------------------------------------------------------------------
extern "C" void kernel_launch(void* const* d_in, const int* in_sizes, int n_in,
                              void* d_out, int out_size) {
    const float* x = (const float*)d_in[0];
    const void* ei = d_in[1];
    const float* W1 = (const float*)d_in[2];
    const float* b1 = (const float*)d_in[3];
    const float* W2 = (const float*)d_in[4];
    const float* b2 = (const float*)d_in[5];
    const float* Wr = (const float*)d_in[6];
    const float* br = (const float*)d_in[7];
    const float* pw = (const float*)d_in[8];
    const float* gamma = (const float*)d_in[9];
    const float* beta = (const float*)d_in[10];
    float* out = (float*)d_out;

    const int N = in_sizes[0] / C_IN;
    const int E = in_sizes[1] / 2;
    const int numTiles = (N + TILE_N - 1) / TILE_N;
    const int G = (E + 3) / 4;

    static int nSM = 0;
    if (nSM == 0) cudaDeviceGetAttribute(&nSM, cudaDevAttrMultiProcessorCount, 0);

    cudaFuncSetAttribute(msg_kernel, cudaFuncAttributeMaxDynamicSharedMemorySize,
                         SMEM_BYTES);

    // K1: persistent per-node MLP + root transform (setup folded into block 0)
    msg_kernel<<<nSM, MT, SMEM_BYTES>>>(x, W1, b1, W2, b2, Wr, br, ei, N, numTiles);

    // K2: edge scatter, 4 edges per 16-thread slot
    const long long units = (long long)G * 16;
    scatter_kernel<<<(int)((units + NT - 1) / NT), NT>>>(ei, E, G);

    // K3: stats (read-only)
    prelu_stats_kernel<<<592, NT>>>(pw, N);

    // K4: PReLU + BN normalize -> out
    bn_kernel<<<592, NT>>>(out, gamma, beta, pw, N);
}